// round 14
// baseline (speedup 1.0000x reference)
#include <cuda_runtime.h>
#include <cstdint>

// InnerProduct_541165879452 on GB300 (sm_103a)
// lp[r,p] = sum_f w[p,f]^2 * sum_e x[r,f,e]^2 ; R=32768, F=64, E=16, P=10.
//
// R10 lesson: register double-buffering capped at DRAM=70% — LDG issue is
// bursty (8 loads / ~30cyc, then ~300cyc memory-silent compute) and deeper
// register pipelines are reg-bound. R11: cp.async.bulk (UBLKCP) smem ring,
// depth 3 x 64KB per SM: load issue decoupled from registers, up to 128KB
// continuously in flight per SM. Compute = same validated warp-per-row
// shfl reduction, now fed from shared memory.

constexpr int R_DIM     = 32768;
constexpr int F_DIM     = 64;
constexpr int P_DIM     = 10;

constexpr int THREADS    = 512;           // 16 warps, one row each per tile
constexpr int TILE_ROWS  = 16;
constexpr int ROW_F4     = 256;           // 1024 floats = 4KB per row
constexpr int TILE_F4    = TILE_ROWS * ROW_F4;     // 4096 float4
constexpr int TILE_BYTES = TILE_F4 * 16;           // 65536
constexpr int DEPTH      = 3;                      // 192KB ring
constexpr int NTILES     = R_DIM / TILE_ROWS;      // 2048
constexpr int NBLOCKS    = 152;                    // 1 per SM (GB300: 152 SMs)
constexpr int NP         = 3;                      // p-slots per lane
constexpr unsigned CHUNK = TILE_BYTES / 4;         // 16KB per bulk copy

__device__ __forceinline__ uint32_t smem_u32(const void* p) {
    return (uint32_t)__cvta_generic_to_shared(p);
}

__device__ __forceinline__ void mbar_wait(uint32_t bar, uint32_t parity) {
    asm volatile(
        "{\n\t"
        ".reg .pred P;\n\t"
        "W_%=:\n\t"
        "mbarrier.try_wait.parity.acquire.cta.shared::cta.b64 P, [%0], %1, 0x989680;\n\t"
        "@P bra D_%=;\n\t"
        "bra W_%=;\n\t"
        "D_%=:\n\t"
        "}"
        :: "r"(bar), "r"(parity) : "memory");
}

__global__ __launch_bounds__(THREADS, 1)
void InnerProduct_541165879452_kernel(const float4* __restrict__ x4,
                                      const float*  __restrict__ w,
                                      float*        __restrict__ out)
{
    extern __shared__ float4 tiles[];                 // DEPTH * TILE_F4
    __shared__ uint64_t mbar[DEPTH];

    const int tid  = threadIdx.x;
    const int wid  = tid >> 5;
    const int lane = tid & 31;
    const int j    = lane >> 2;     // f-slot within batch
    const int c    = lane & 3;      // e-quarter / p-group

    if (tid < DEPTH) {
        asm volatile("mbarrier.init.shared.b64 [%0], 1;"
                     :: "r"(smem_u32(&mbar[tid])) : "memory");
    }
    __syncthreads();

    // Squared weights in registers (2.5KB tensor, L2-hot), fixed per lane.
    float wreg[8][NP];
    #pragma unroll
    for (int k = 0; k < 8; k++) {
        #pragma unroll
        for (int i = 0; i < NP; i++) {
            int p = c + 4 * i;
            float v = (p < P_DIM) ? w[p * F_DIM + (8 * k + j)] : 0.0f;
            wreg[k][i] = v * v;
        }
    }

    // This block's tile sequence: t(n) = blockIdx.x + n*NBLOCKS
    const int NT = (NTILES - blockIdx.x + NBLOCKS - 1) / NBLOCKS;

    auto produce = [&](int s, int n) {
        long long t = blockIdx.x + (long long)n * NBLOCKS;
        const char* src = (const char*)(x4 + t * (long long)TILE_F4);
        uint32_t dst = smem_u32(tiles + s * TILE_F4);
        uint32_t bar = smem_u32(&mbar[s]);
        asm volatile("mbarrier.arrive.expect_tx.shared.b64 _, [%0], %1;"
                     :: "r"(bar), "r"((unsigned)TILE_BYTES) : "memory");
        #pragma unroll
        for (unsigned q = 0; q < 4; q++) {
            asm volatile(
                "cp.async.bulk.shared::cta.global.mbarrier::complete_tx::bytes "
                "[%0], [%1], %2, [%3];"
                :: "r"(dst + q * CHUNK), "l"(src + (size_t)q * CHUNK),
                   "r"(CHUNK), "r"(bar) : "memory");
        }
    };

    // Prologue: fill the ring (stages never consumed yet -> no empty wait).
    if (tid == 0) {
        for (int d = 0; d < DEPTH && d < NT; d++) produce(d, d);
    }

    for (int n = 0; n < NT; n++) {
        const int s = n % DEPTH;
        const uint32_t parity = (uint32_t)((n / DEPTH) & 1);
        mbar_wait(smem_u32(&mbar[s]), parity);

        const long long t = blockIdx.x + (long long)n * NBLOCKS;
        const long long r = t * TILE_ROWS + wid;
        const float4* rowp = tiles + s * TILE_F4 + wid * ROW_F4;

        // Stage this warp's 4KB row from smem (conflict-free LDS.128).
        float4 v[8];
        #pragma unroll
        for (int k = 0; k < 8; k++)
            v[k] = rowp[k * 32 + lane];

        float acc[NP] = {0.0f, 0.0f, 0.0f};
        #pragma unroll
        for (int k = 0; k < 8; k++) {
            float s4 = v[k].x * v[k].x + v[k].y * v[k].y
                     + v[k].z * v[k].z + v[k].w * v[k].w;
            // e-reduction across the quarter-warp: all 4 lanes get xsq[r][f]
            s4 += __shfl_xor_sync(0xffffffffu, s4, 1);
            s4 += __shfl_xor_sync(0xffffffffu, s4, 2);
            #pragma unroll
            for (int i = 0; i < NP; i++)
                acc[i] += wreg[k][i] * s4;
        }
        // f-reduction over j (lane bits 2..4)
        #pragma unroll
        for (int i = 0; i < NP; i++) {
            acc[i] += __shfl_xor_sync(0xffffffffu, acc[i], 4);
            acc[i] += __shfl_xor_sync(0xffffffffu, acc[i], 8);
            acc[i] += __shfl_xor_sync(0xffffffffu, acc[i], 16);
        }
        if (lane < 4) {
            #pragma unroll
            for (int i = 0; i < NP; i++) {
                int p = c + 4 * i;
                if (p < P_DIM)
                    out[r * P_DIM + p] = acc[i];
            }
        }

        __syncthreads();                       // stage s fully consumed
        if (tid == 0 && n + DEPTH < NT)
            produce(s, n + DEPTH);             // refill stage s
    }
}

extern "C" void kernel_launch(void* const* d_in, const int* in_sizes, int n_in,
                              void* d_out, int out_size)
{
    const float4* x4 = (const float4*)d_in[0];   // x: [R, F, E] fp32
    const float*  w  = (const float*) d_in[1];   // weights: [P, F] fp32
    float* out = (float*)d_out;                  // [R, P] fp32

    (void)in_sizes; (void)n_in; (void)out_size;

    cudaFuncSetAttribute(InnerProduct_541165879452_kernel,
                         cudaFuncAttributeMaxDynamicSharedMemorySize,
                         DEPTH * TILE_BYTES);
    InnerProduct_541165879452_kernel<<<NBLOCKS, THREADS, DEPTH * TILE_BYTES>>>(x4, w, out);
}

// round 16
// speedup vs baseline: 1.0083x; 1.0083x over previous
#include <cuda_runtime.h>
#include <cstdint>

// InnerProduct_541165879452 on GB300 (sm_103a)
// lp[r,p] = sum_f w[p,f]^2 * sum_e x[r,f,e]^2 ; R=32768, F=64, E=16, P=10.
//
// R14 lesson: ring refill gated by full-block __syncthreads after the whole
// compute phase -> DRAM demand gaps, 69.5% DRAM (same plateau as the LDG
// pipeline). R15: warp-specialized producer + per-stage full/empty mbarriers;
// consumers release a stage immediately after register staging (before the
// shfl/FMA phase); 2 blocks/SM to desynchronize; no __syncthreads in the loop.

constexpr int R_DIM      = 32768;
constexpr int F_DIM      = 64;
constexpr int P_DIM      = 10;

constexpr int CONS_WARPS = 8;
constexpr int THREADS    = (CONS_WARPS + 1) * 32;   // 288: 8 consumers + 1 producer
constexpr int TILE_ROWS  = 8;
constexpr int ROW_F4     = 256;                     // 1024 floats = 4KB/row
constexpr int TILE_F4    = TILE_ROWS * ROW_F4;      // 2048 float4
constexpr int TILE_BYTES = TILE_F4 * 16;            // 32768
constexpr int DEPTH      = 3;                       // 96KB ring per block
constexpr int NTILES     = R_DIM / TILE_ROWS;       // 4096
constexpr int NBLOCKS    = 304;                     // 2 per SM
constexpr int NP         = 3;                       // p-slots per lane
constexpr unsigned CHUNK = TILE_BYTES / 2;          // 16KB per bulk copy

__device__ __forceinline__ uint32_t smem_u32(const void* p) {
    return (uint32_t)__cvta_generic_to_shared(p);
}

__device__ __forceinline__ void mbar_wait(uint32_t bar, uint32_t parity) {
    asm volatile(
        "{\n\t"
        ".reg .pred P;\n\t"
        "W_%=:\n\t"
        "mbarrier.try_wait.parity.acquire.cta.shared::cta.b64 P, [%0], %1, 0x989680;\n\t"
        "@P bra D_%=;\n\t"
        "bra W_%=;\n\t"
        "D_%=:\n\t"
        "}"
        :: "r"(bar), "r"(parity) : "memory");
}

__global__ __launch_bounds__(THREADS, 2)
void InnerProduct_541165879452_kernel(const float4* __restrict__ x4,
                                      const float*  __restrict__ w,
                                      float*        __restrict__ out)
{
    extern __shared__ float4 tiles[];            // DEPTH * TILE_F4
    __shared__ uint64_t full_bar[DEPTH];
    __shared__ uint64_t empty_bar[DEPTH];

    const int tid  = threadIdx.x;
    const int wid  = tid >> 5;
    const int lane = tid & 31;

    if (tid < DEPTH) {
        asm volatile("mbarrier.init.shared.b64 [%0], 1;"
                     :: "r"(smem_u32(&full_bar[tid])) : "memory");
    } else if (tid < 2 * DEPTH) {
        asm volatile("mbarrier.init.shared.b64 [%0], %1;"
                     :: "r"(smem_u32(&empty_bar[tid - DEPTH])),
                        "r"((unsigned)CONS_WARPS) : "memory");
    }
    __syncthreads();

    // Tiles for this block: t(n) = blockIdx.x + n*NBLOCKS  (t < NTILES)
    const int NT = (NTILES - blockIdx.x + NBLOCKS - 1) / NBLOCKS;

    if (wid == CONS_WARPS) {
        // ---- producer warp (lane 0 only) --------------------------------
        if (lane == 0) {
            for (int n = 0; n < NT; n++) {
                const int s = n % DEPTH;
                // producer starts at phase 1: first DEPTH waits pass trivially
                const uint32_t ppar = (uint32_t)(((n / DEPTH) & 1) ^ 1);
                mbar_wait(smem_u32(&empty_bar[s]), ppar);

                const long long t = blockIdx.x + (long long)n * NBLOCKS;
                const char* src = (const char*)(x4 + t * (long long)TILE_F4);
                const uint32_t dst = smem_u32(tiles + s * TILE_F4);
                const uint32_t bar = smem_u32(&full_bar[s]);
                asm volatile("mbarrier.arrive.expect_tx.shared.b64 _, [%0], %1;"
                             :: "r"(bar), "r"((unsigned)TILE_BYTES) : "memory");
                #pragma unroll
                for (unsigned q = 0; q < 2; q++) {
                    asm volatile(
                        "cp.async.bulk.shared::cta.global.mbarrier::complete_tx::bytes "
                        "[%0], [%1], %2, [%3];"
                        :: "r"(dst + q * CHUNK), "l"(src + (size_t)q * CHUNK),
                           "r"(CHUNK), "r"(bar) : "memory");
                }
            }
        }
        return;
    }

    // ---- consumer warps 0..7: one row per tile ---------------------------
    const int j = lane >> 2;     // f-slot within batch
    const int c = lane & 3;      // e-quarter / p-group

    // Squared weights in registers (2.5KB, L2-hot), fixed per lane.
    float wreg[8][NP];
    #pragma unroll
    for (int k = 0; k < 8; k++) {
        #pragma unroll
        for (int i = 0; i < NP; i++) {
            int p = c + 4 * i;
            float v = (p < P_DIM) ? w[p * F_DIM + (8 * k + j)] : 0.0f;
            wreg[k][i] = v * v;
        }
    }

    for (int n = 0; n < NT; n++) {
        const int s = n % DEPTH;
        const uint32_t cpar = (uint32_t)((n / DEPTH) & 1);
        mbar_wait(smem_u32(&full_bar[s]), cpar);

        // Stage this warp's 4KB row (conflict-free LDS.128), then RELEASE
        // the stage before compute so the producer can refill immediately.
        const float4* rowp = tiles + s * TILE_F4 + wid * ROW_F4;
        float4 v[8];
        #pragma unroll
        for (int k = 0; k < 8; k++)
            v[k] = rowp[k * 32 + lane];

        if (lane == 0) {
            asm volatile("mbarrier.arrive.release.cta.shared::cta.b64 _, [%0];"
                         :: "r"(smem_u32(&empty_bar[s])) : "memory");
        }

        float acc[NP] = {0.0f, 0.0f, 0.0f};
        #pragma unroll
        for (int k = 0; k < 8; k++) {
            float s4 = v[k].x * v[k].x + v[k].y * v[k].y
                     + v[k].z * v[k].z + v[k].w * v[k].w;
            // e-reduction across the quarter-warp: all 4 lanes get xsq[r][f]
            s4 += __shfl_xor_sync(0xffffffffu, s4, 1);
            s4 += __shfl_xor_sync(0xffffffffu, s4, 2);
            #pragma unroll
            for (int i = 0; i < NP; i++)
                acc[i] += wreg[k][i] * s4;
        }
        // f-reduction over j (lane bits 2..4)
        #pragma unroll
        for (int i = 0; i < NP; i++) {
            acc[i] += __shfl_xor_sync(0xffffffffu, acc[i], 4);
            acc[i] += __shfl_xor_sync(0xffffffffu, acc[i], 8);
            acc[i] += __shfl_xor_sync(0xffffffffu, acc[i], 16);
        }

        const long long t = blockIdx.x + (long long)n * NBLOCKS;
        const long long r = t * TILE_ROWS + wid;
        if (lane < 4) {
            #pragma unroll
            for (int i = 0; i < NP; i++) {
                int p = c + 4 * i;
                if (p < P_DIM)
                    out[r * P_DIM + p] = acc[i];
            }
        }
    }
}

extern "C" void kernel_launch(void* const* d_in, const int* in_sizes, int n_in,
                              void* d_out, int out_size)
{
    const float4* x4 = (const float4*)d_in[0];   // x: [R, F, E] fp32
    const float*  w  = (const float*) d_in[1];   // weights: [P, F] fp32
    float* out = (float*)d_out;                  // [R, P] fp32

    (void)in_sizes; (void)n_in; (void)out_size;

    cudaFuncSetAttribute(InnerProduct_541165879452_kernel,
                         cudaFuncAttributeMaxDynamicSharedMemorySize,
                         DEPTH * TILE_BYTES);
    InnerProduct_541165879452_kernel<<<NBLOCKS, THREADS, DEPTH * TILE_BYTES>>>(x4, w, out);
}

// round 17
// speedup vs baseline: 1.0240x; 1.0156x over previous
#include <cuda_runtime.h>
#include <cstdint>

// InnerProduct_541165879452 on GB300 (sm_103a)
// lp[r,p] = sum_f w[p,f]^2 * sum_e x[r,f,e]^2 ; R=32768, F=64, E=16, P=10.
//
// R16 experiment: three independent designs (LDG pipeline, TMA ring x2) all
// plateau at 5.4-5.6 TB/s with every intermediate unit underutilized ->
// hypothesis: per-SM request-concurrency cap in EACH path (TMA engine window,
// LDG scoreboard/duty-cycle). This kernel drives BOTH engines concurrently:
// rows [0, R/2) via the warp-specialized TMA ring, rows [R/2, R) via direct
// staged LDG.128 in the same consumer warps (issued before the mbar poll so
// they are in flight during the wait).

constexpr int R_DIM      = 32768;
constexpr int F_DIM      = 64;
constexpr int P_DIM      = 10;

constexpr int CONS_WARPS = 8;
constexpr int THREADS    = (CONS_WARPS + 1) * 32;   // 288
constexpr int TILE_ROWS  = 8;
constexpr int ROW_F4     = 256;                     // 4KB per row
constexpr int TILE_F4    = TILE_ROWS * ROW_F4;      // 2048 float4
constexpr int TILE_BYTES = TILE_F4 * 16;            // 32768
constexpr int DEPTH      = 3;                       // 96KB ring per block
constexpr int NBLOCKS    = 304;                     // 2 per SM
constexpr int NP         = 3;

// Row split between the two engines
constexpr int R_TMA       = R_DIM / 2;              // rows 0..16383 via TMA
constexpr int NTILES_TMA  = R_TMA / TILE_ROWS;      // 2048 tiles
constexpr int GWARPS      = NBLOCKS * CONS_WARPS;   // 2432 LDG streams
constexpr unsigned CHUNK  = TILE_BYTES / 2;         // 16KB per bulk copy

__device__ __forceinline__ uint32_t smem_u32(const void* p) {
    return (uint32_t)__cvta_generic_to_shared(p);
}

__device__ __forceinline__ void mbar_wait(uint32_t bar, uint32_t parity) {
    asm volatile(
        "{\n\t"
        ".reg .pred P;\n\t"
        "W_%=:\n\t"
        "mbarrier.try_wait.parity.acquire.cta.shared::cta.b64 P, [%0], %1, 0x989680;\n\t"
        "@P bra D_%=;\n\t"
        "bra W_%=;\n\t"
        "D_%=:\n\t"
        "}"
        :: "r"(bar), "r"(parity) : "memory");
}

__global__ __launch_bounds__(THREADS, 2)
void InnerProduct_541165879452_kernel(const float4* __restrict__ x4,
                                      const float*  __restrict__ w,
                                      float*        __restrict__ out)
{
    extern __shared__ float4 tiles[];            // DEPTH * TILE_F4
    __shared__ uint64_t full_bar[DEPTH];
    __shared__ uint64_t empty_bar[DEPTH];

    const int tid  = threadIdx.x;
    const int wid  = tid >> 5;
    const int lane = tid & 31;

    if (tid < DEPTH) {
        asm volatile("mbarrier.init.shared.b64 [%0], 1;"
                     :: "r"(smem_u32(&full_bar[tid])) : "memory");
    } else if (tid < 2 * DEPTH) {
        asm volatile("mbarrier.init.shared.b64 [%0], %1;"
                     :: "r"(smem_u32(&empty_bar[tid - DEPTH])),
                        "r"((unsigned)CONS_WARPS) : "memory");
    }
    __syncthreads();

    // TMA tiles for this block: t = blockIdx.x + n*NBLOCKS < NTILES_TMA
    const int NT = (NTILES_TMA - blockIdx.x + NBLOCKS - 1) / NBLOCKS;

    if (wid == CONS_WARPS) {
        // ---- producer warp (lane 0): feed the TMA ring -------------------
        if (lane == 0) {
            for (int n = 0; n < NT; n++) {
                const int s = n % DEPTH;
                const uint32_t ppar = (uint32_t)(((n / DEPTH) & 1) ^ 1);
                mbar_wait(smem_u32(&empty_bar[s]), ppar);

                const long long t = blockIdx.x + (long long)n * NBLOCKS;
                const char* src = (const char*)(x4 + t * (long long)TILE_F4);
                const uint32_t dst = smem_u32(tiles + s * TILE_F4);
                const uint32_t bar = smem_u32(&full_bar[s]);
                asm volatile("mbarrier.arrive.expect_tx.shared.b64 _, [%0], %1;"
                             :: "r"(bar), "r"((unsigned)TILE_BYTES) : "memory");
                #pragma unroll
                for (unsigned q = 0; q < 2; q++) {
                    asm volatile(
                        "cp.async.bulk.shared::cta.global.mbarrier::complete_tx::bytes "
                        "[%0], [%1], %2, [%3];"
                        :: "r"(dst + q * CHUNK), "l"(src + (size_t)q * CHUNK),
                           "r"(CHUNK), "r"(bar) : "memory");
                }
            }
        }
        return;
    }

    // ---- consumer warps 0..7 --------------------------------------------
    const int j = lane >> 2;     // f-slot within batch
    const int c = lane & 3;      // e-quarter / p-group

    float wreg[8][NP];
    #pragma unroll
    for (int k = 0; k < 8; k++) {
        #pragma unroll
        for (int i = 0; i < NP; i++) {
            int p = c + 4 * i;
            float v = (p < P_DIM) ? w[p * F_DIM + (8 * k + j)] : 0.0f;
            wreg[k][i] = v * v;
        }
    }

    // Row reduce+store from a staged register buffer.
    auto compute_row = [&](const float4 (&v)[8], long long r) {
        float acc[NP] = {0.0f, 0.0f, 0.0f};
        #pragma unroll
        for (int k = 0; k < 8; k++) {
            float s4 = v[k].x * v[k].x + v[k].y * v[k].y
                     + v[k].z * v[k].z + v[k].w * v[k].w;
            s4 += __shfl_xor_sync(0xffffffffu, s4, 1);
            s4 += __shfl_xor_sync(0xffffffffu, s4, 2);
            #pragma unroll
            for (int i = 0; i < NP; i++)
                acc[i] += wreg[k][i] * s4;
        }
        #pragma unroll
        for (int i = 0; i < NP; i++) {
            acc[i] += __shfl_xor_sync(0xffffffffu, acc[i], 4);
            acc[i] += __shfl_xor_sync(0xffffffffu, acc[i], 8);
            acc[i] += __shfl_xor_sync(0xffffffffu, acc[i], 16);
        }
        if (lane < 4) {
            #pragma unroll
            for (int i = 0; i < NP; i++) {
                int p = c + 4 * i;
                if (p < P_DIM)
                    out[r * P_DIM + p] = acc[i];
            }
        }
    };

    const int gid = blockIdx.x * CONS_WARPS + wid;   // global LDG-stream id

    int n = 0;
    long long rg = R_TMA + gid;                      // this warp's LDG rows
    while (n < NT || rg < R_DIM) {
        // 1) Issue the direct-LDG batch FIRST: in flight during the mbar poll.
        const bool has_g = (rg < R_DIM);
        float4 vg[8];
        if (has_g) {
            const float4* xr = x4 + rg * (long long)ROW_F4;
            #pragma unroll
            for (int k = 0; k < 8; k++)
                vg[k] = xr[k * 32 + lane];
        }

        // 2) TMA-ring row: wait, stage, release stage, compute.
        if (n < NT) {
            const int s = n % DEPTH;
            const uint32_t cpar = (uint32_t)((n / DEPTH) & 1);
            mbar_wait(smem_u32(&full_bar[s]), cpar);

            const float4* rowp = tiles + s * TILE_F4 + wid * ROW_F4;
            float4 vt[8];
            #pragma unroll
            for (int k = 0; k < 8; k++)
                vt[k] = rowp[k * 32 + lane];

            if (lane == 0) {
                asm volatile("mbarrier.arrive.release.cta.shared::cta.b64 _, [%0];"
                             :: "r"(smem_u32(&empty_bar[s])) : "memory");
            }

            const long long t = blockIdx.x + (long long)n * NBLOCKS;
            compute_row(vt, t * TILE_ROWS + wid);
        }

        // 3) Direct-LDG row compute (data arrived during step 2).
        if (has_g) {
            compute_row(vg, rg);
            rg += GWARPS;
        }
        n++;
    }
}

extern "C" void kernel_launch(void* const* d_in, const int* in_sizes, int n_in,
                              void* d_out, int out_size)
{
    const float4* x4 = (const float4*)d_in[0];   // x: [R, F, E] fp32
    const float*  w  = (const float*) d_in[1];   // weights: [P, F] fp32
    float* out = (float*)d_out;                  // [R, P] fp32

    (void)in_sizes; (void)n_in; (void)out_size;

    cudaFuncSetAttribute(InnerProduct_541165879452_kernel,
                         cudaFuncAttributeMaxDynamicSharedMemorySize,
                         DEPTH * TILE_BYTES);
    InnerProduct_541165879452_kernel<<<NBLOCKS, THREADS, DEPTH * TILE_BYTES>>>(x4, w, out);
}